// round 6
// baseline (speedup 1.0000x reference)
#include <cuda_runtime.h>

#define HH 32
#define WW 32
#define BB 16
#define NPOS 512
#define PIX 4              // pixels per block (all in one row)
#define THREADS 512
#define GRID 256
#define SEGROW 36          // floats per A-segment (32 data + 4 pad), 16B-aligned
#define SROW (16 * SEGROW + 4)   // 580 floats per pixel row, 16B-aligned
#define LHW (NPOS * HH * WW)

// Ping-pong state scratch (no device allocation allowed).
__device__ float g_state[2][BB * HH * WW];

__device__ __forceinline__ float sigmoidf(float x) {
    return __fdividef(1.0f, 1.0f + __expf(-x));
}

// 8 products for one bit-triple (va = MSB).
__device__ __forceinline__ void triple8(float va, float vb, float vc, float* P) {
    float ca = 1.0f - va, cb = 1.0f - vb, cc = 1.0f - vc;
    float t0 = cb * cc, t1 = cb * vc, t2 = vb * cc, t3 = vb * vc;
    P[0] = ca * t0; P[1] = ca * t1; P[2] = ca * t2; P[3] = ca * t3;
    P[4] = va * t0; P[5] = va * t1; P[6] = va * t2; P[7] = va * t3;
}

__global__ __launch_bounds__(THREADS, 4)
void asic_layer(const float* __restrict__ src,   // (B,H,W) previous state
                const float* __restrict__ tg,    // (NPOS,H,W) this layer's gates
                float* __restrict__ dst)         // (B,H,W)
{
    __shared__ __align__(16) float s_s[PIX * SROW];

    const int tid = threadIdx.x;
    const int pixBase = blockIdx.x * PIX;

    // ---- stage + sigmoid: one combo p per thread, 4 pixels via LDG.128 ----
    {
        int p = tid;                                    // combo 0..511
        float4 g = *(const float4*)(tg + p * (HH * WW) + pixBase);
        int base = (p >> 5) * SEGROW + (p & 31);
        s_s[0 * SROW + base] = sigmoidf(g.x);
        s_s[1 * SROW + base] = sigmoidf(g.y);
        s_s[2 * SROW + base] = sigmoidf(g.z);
        s_s[3 * SROW + base] = sigmoidf(g.w);
    }
    __syncthreads();

    // ---- thread mapping: seg(16) x batch-pair(8) x pixel(4) ----
    const int seg  = tid & 15;           // A = top 4 bits of combo j
    const int bp   = (tid >> 4) & 7;     // batches bp and bp+8
    const int pixL = tid >> 7;           // 0..3
    const int pixel = pixBase + pixL;
    const int h = pixel >> 5;
    const int w = pixel & 31;
    const int b0 = bp, b1 = bp + 8;

    // ---- gather 3x3 wrapped windows for both batches ----
    float v0[9], v1[9];
#pragma unroll
    for (int i0 = 0; i0 < 3; i0++) {
        int hh = h + i0; if (hh >= HH) hh -= HH;
#pragma unroll
        for (int i1 = 0; i1 < 3; i1++) {
            int ww2 = w + i1 - 1;
            if (ww2 < 0) ww2 += WW;
            if (ww2 >= WW) ww2 -= WW;
            int spat = hh * WW + ww2;
            v0[i0 * 3 + i1] = __ldg(src + b0 * (HH * WW) + spat);
            v1[i0 * 3 + i1] = __ldg(src + b1 * (HH * WW) + spat);
        }
    }

    // ---- partial products ----
    // bit for elem m is (j >> (8-m)) & 1:
    // A = j>>5 (m0..m3, fixed = seg), B = (j>>2)&7 (m4..m6), C = j&3 (m7,m8)
    float PB0[8], PB1[8];
    triple8(v0[4], v0[5], v0[6], PB0);
    triple8(v1[4], v1[5], v1[6], PB1);

    float PC0[4], PC1[4];
    {
        float c7 = 1.0f - v0[7], c8 = 1.0f - v0[8];
        PC0[0] = c7 * c8; PC0[1] = c7 * v0[8]; PC0[2] = v0[7] * c8; PC0[3] = v0[7] * v0[8];
        float d7 = 1.0f - v1[7], d8 = 1.0f - v1[8];
        PC1[0] = d7 * d8; PC1[1] = d7 * v1[8]; PC1[2] = v1[7] * d8; PC1[3] = v1[7] * v1[8];
    }

    const float PA0 = ((seg & 8) ? v0[0] : 1.0f - v0[0])
                    * ((seg & 4) ? v0[1] : 1.0f - v0[1])
                    * ((seg & 2) ? v0[2] : 1.0f - v0[2])
                    * ((seg & 1) ? v0[3] : 1.0f - v0[3]);
    const float PA1 = ((seg & 8) ? v1[0] : 1.0f - v1[0])
                    * ((seg & 4) ? v1[1] : 1.0f - v1[1])
                    * ((seg & 2) ? v1[2] : 1.0f - v1[2])
                    * ((seg & 1) ? v1[3] : 1.0f - v1[3]);

    // ---- contraction: this thread's 32 combos, both batches per gate read ----
    const float* sp = s_s + pixL * SROW + seg * SEGROW;
    float a0e = 0.0f, a0o = 0.0f, a1e = 0.0f, a1o = 0.0f;
#pragma unroll
    for (int q = 0; q < 8; q += 2) {
        float4 r0 = *(const float4*)(sp + q * 4);
        float4 r1 = *(const float4*)(sp + q * 4 + 4);
        float i00 = (PC0[0] * r0.x + PC0[1] * r0.y) + (PC0[2] * r0.z + PC0[3] * r0.w);
        float i10 = (PC1[0] * r0.x + PC1[1] * r0.y) + (PC1[2] * r0.z + PC1[3] * r0.w);
        float i01 = (PC0[0] * r1.x + PC0[1] * r1.y) + (PC0[2] * r1.z + PC0[3] * r1.w);
        float i11 = (PC1[0] * r1.x + PC1[1] * r1.y) + (PC1[2] * r1.z + PC1[3] * r1.w);
        a0e = fmaf(PB0[q], i00, a0e);
        a1e = fmaf(PB1[q], i10, a1e);
        a0o = fmaf(PB0[q + 1], i01, a0o);
        a1o = fmaf(PB1[q + 1], i11, a1o);
    }
    float acc0 = PA0 * (a0e + a0o);
    float acc1 = PA1 * (a1e + a1o);

    // ---- reduce over the 16 A-segment lanes (seg = lane bits 0..3) ----
#pragma unroll
    for (int d = 1; d <= 8; d <<= 1) {
        acc0 += __shfl_xor_sync(0xffffffffu, acc0, d);
        acc1 += __shfl_xor_sync(0xffffffffu, acc1, d);
    }

    if (seg == 0) {
        dst[b0 * (HH * WW) + pixel] = fminf(fmaxf(acc0, 0.0f), 1.0f);
        dst[b1 * (HH * WW) + pixel] = fminf(fmaxf(acc1, 0.0f), 1.0f);
    }
}

extern "C" void kernel_launch(void* const* d_in, const int* in_sizes, int n_in,
                              void* d_out, int out_size) {
    // Identify inputs by size (x: 16384, tg: 2097152)
    const float* x  = (const float*)d_in[0];
    const float* tg = (const float*)d_in[1];
    if (n_in >= 2 && in_sizes[0] > in_sizes[1]) {
        x  = (const float*)d_in[1];
        tg = (const float*)d_in[0];
    }
    float* out = (float*)d_out;

    float* st;
    cudaGetSymbolAddress((void**)&st, g_state);
    float* s0 = st;
    float* s1 = st + BB * HH * WW;

    asic_layer<<<GRID, THREADS>>>(x,  tg + 0 * LHW, s0);
    asic_layer<<<GRID, THREADS>>>(s0, tg + 1 * LHW, s1);
    asic_layer<<<GRID, THREADS>>>(s1, tg + 2 * LHW, s0);
    asic_layer<<<GRID, THREADS>>>(s0, tg + 3 * LHW, out);
}

// round 7
// speedup vs baseline: 1.2405x; 1.2405x over previous
#include <cuda_runtime.h>

#define HH 32
#define WW 32
#define BB 16
#define NPOS 512
#define PIX 8              // pixels per block (row-contiguous quarter... 8 | 32)
#define THREADS 1024
#define GRID 128
#define SEGROW 36          // floats per A-segment (32 data + 4 pad)
#define SROW (16 * SEGROW + 4)   // 580 floats per pixel row
#define LHW (NPOS * HH * WW)

// Ping-pong state scratch (no device allocation allowed).
__device__ float g_state[2][BB * HH * WW];

__device__ __forceinline__ float sigmoidf(float x) {
    return __fdividef(1.0f, 1.0f + __expf(-x));
}

// 8 products for one bit-triple (va = MSB).
__device__ __forceinline__ void triple8(float va, float vb, float vc, float* P) {
    float ca = 1.0f - va, cb = 1.0f - vb, cc = 1.0f - vc;
    float t0 = cb * cc, t1 = cb * vc, t2 = vb * cc, t3 = vb * vc;
    P[0] = ca * t0; P[1] = ca * t1; P[2] = ca * t2; P[3] = ca * t3;
    P[4] = va * t0; P[5] = va * t1; P[6] = va * t2; P[7] = va * t3;
}

__global__ __launch_bounds__(THREADS, 1)
void asic_layer(const float* __restrict__ src,   // (B,H,W) previous state
                const float* __restrict__ tg,    // (NPOS,H,W) this layer's gates
                float* __restrict__ dst)         // (B,H,W)
{
    __shared__ __align__(16) float s_s[PIX * SROW];

    const int tid = threadIdx.x;
    const int pixBase = blockIdx.x * PIX;

    // ---- thread mapping: seg(16) x batch-pair(8) x pixel(8) ----
    const int seg  = tid & 15;           // A = top 4 bits of combo j
    const int bp   = (tid >> 4) & 7;     // batches bp and bp+8
    const int pixL = tid >> 7;           // 0..7
    const int pixel = pixBase + pixL;
    const int h = pixel >> 5;
    const int w = pixel & 31;
    const int b0 = bp, b1 = bp + 8;

    // ---- issue gate LDG.128 (one combo-halfrow per thread) ----
    const int p  = tid >> 1;             // combo 0..511
    const int ih = (tid & 1) * 4;        // pixels ih..ih+3
    float4 g = *(const float4*)(tg + p * (HH * WW) + pixBase + ih);

    // ---- issue window LDGs early (latency overlaps staging below) ----
    float v0[9], v1[9];
#pragma unroll
    for (int i0 = 0; i0 < 3; i0++) {
        int hh = h + i0; if (hh >= HH) hh -= HH;
#pragma unroll
        for (int i1 = 0; i1 < 3; i1++) {
            int ww2 = w + i1 - 1;
            if (ww2 < 0) ww2 += WW;
            if (ww2 >= WW) ww2 -= WW;
            int spat = hh * WW + ww2;
            v0[i0 * 3 + i1] = __ldg(src + b0 * (HH * WW) + spat);
            v1[i0 * 3 + i1] = __ldg(src + b1 * (HH * WW) + spat);
        }
    }

    // ---- stage sigmoid(gates) (conflict-free skewed layout) ----
    {
        int base = (p >> 5) * SEGROW + (p & 31);
        s_s[(ih + 0) * SROW + base] = sigmoidf(g.x);
        s_s[(ih + 1) * SROW + base] = sigmoidf(g.y);
        s_s[(ih + 2) * SROW + base] = sigmoidf(g.z);
        s_s[(ih + 3) * SROW + base] = sigmoidf(g.w);
    }
    __syncthreads();

    // ---- partial products ----
    // bit for elem m is (j >> (8-m)) & 1:
    // A = j>>5 (m0..m3, fixed = seg), B = (j>>2)&7 (m4..m6), C = j&3 (m7,m8)
    float PB0[8], PB1[8];
    triple8(v0[4], v0[5], v0[6], PB0);
    triple8(v1[4], v1[5], v1[6], PB1);

    float PC0[4], PC1[4];
    {
        float c7 = 1.0f - v0[7], c8 = 1.0f - v0[8];
        PC0[0] = c7 * c8; PC0[1] = c7 * v0[8]; PC0[2] = v0[7] * c8; PC0[3] = v0[7] * v0[8];
        float d7 = 1.0f - v1[7], d8 = 1.0f - v1[8];
        PC1[0] = d7 * d8; PC1[1] = d7 * v1[8]; PC1[2] = v1[7] * d8; PC1[3] = v1[7] * v1[8];
    }

    const float PA0 = (((seg & 8) ? v0[0] : 1.0f - v0[0]) * ((seg & 4) ? v0[1] : 1.0f - v0[1]))
                    * (((seg & 2) ? v0[2] : 1.0f - v0[2]) * ((seg & 1) ? v0[3] : 1.0f - v0[3]));
    const float PA1 = (((seg & 8) ? v1[0] : 1.0f - v1[0]) * ((seg & 4) ? v1[1] : 1.0f - v1[1]))
                    * (((seg & 2) ? v1[2] : 1.0f - v1[2]) * ((seg & 1) ? v1[3] : 1.0f - v1[3]));

    // ---- contraction: 32 combos, fma chains, each gate read feeds 2 batches ----
    const float* sp = s_s + pixL * SROW + seg * SEGROW;
    float a0e = 0.0f, a0o = 0.0f, a1e = 0.0f, a1o = 0.0f;
#pragma unroll
    for (int b = 0; b < 8; b += 2) {
        float4 r0 = *(const float4*)(sp + b * 4);
        float4 r1 = *(const float4*)(sp + b * 4 + 4);

        float i00 = PC0[0] * r0.x;
        i00 = fmaf(PC0[1], r0.y, i00);
        i00 = fmaf(PC0[2], r0.z, i00);
        i00 = fmaf(PC0[3], r0.w, i00);
        float i10 = PC1[0] * r0.x;
        i10 = fmaf(PC1[1], r0.y, i10);
        i10 = fmaf(PC1[2], r0.z, i10);
        i10 = fmaf(PC1[3], r0.w, i10);
        float i01 = PC0[0] * r1.x;
        i01 = fmaf(PC0[1], r1.y, i01);
        i01 = fmaf(PC0[2], r1.z, i01);
        i01 = fmaf(PC0[3], r1.w, i01);
        float i11 = PC1[0] * r1.x;
        i11 = fmaf(PC1[1], r1.y, i11);
        i11 = fmaf(PC1[2], r1.z, i11);
        i11 = fmaf(PC1[3], r1.w, i11);

        a0e = fmaf(PB0[b], i00, a0e);
        a1e = fmaf(PB1[b], i10, a1e);
        a0o = fmaf(PB0[b + 1], i01, a0o);
        a1o = fmaf(PB1[b + 1], i11, a1o);
    }
    float acc0 = PA0 * (a0e + a0o);
    float acc1 = PA1 * (a1e + a1o);

    // ---- reduce over the 16 A-segment lanes (seg = lane bits 0..3) ----
#pragma unroll
    for (int d = 1; d <= 8; d <<= 1) {
        acc0 += __shfl_xor_sync(0xffffffffu, acc0, d);
        acc1 += __shfl_xor_sync(0xffffffffu, acc1, d);
    }

    if (seg == 0) {
        dst[b0 * (HH * WW) + pixel] = fminf(fmaxf(acc0, 0.0f), 1.0f);
        dst[b1 * (HH * WW) + pixel] = fminf(fmaxf(acc1, 0.0f), 1.0f);
    }
}

extern "C" void kernel_launch(void* const* d_in, const int* in_sizes, int n_in,
                              void* d_out, int out_size) {
    // Identify inputs by size (x: 16384, tg: 2097152)
    const float* x  = (const float*)d_in[0];
    const float* tg = (const float*)d_in[1];
    if (n_in >= 2 && in_sizes[0] > in_sizes[1]) {
        x  = (const float*)d_in[1];
        tg = (const float*)d_in[0];
    }
    float* out = (float*)d_out;

    float* st;
    cudaGetSymbolAddress((void**)&st, g_state);
    float* s0 = st;
    float* s1 = st + BB * HH * WW;

    asic_layer<<<GRID, THREADS>>>(x,  tg + 0 * LHW, s0);
    asic_layer<<<GRID, THREADS>>>(s0, tg + 1 * LHW, s1);
    asic_layer<<<GRID, THREADS>>>(s1, tg + 2 * LHW, s0);
    asic_layer<<<GRID, THREADS>>>(s0, tg + 3 * LHW, out);
}

// round 8
// speedup vs baseline: 1.2429x; 1.0019x over previous
#include <cuda_runtime.h>

#define HH 32
#define WW 32
#define BB 16
#define NPOS 512
#define PIX 8              // pixels per block (contiguous in one row; 8 | 32)
#define THREADS 1024
#define GRID 128
#define SEGROW 36          // floats per A-segment (32 data + 4 pad)
#define SROW (16 * SEGROW + 4)   // 580 floats per pixel row
#define LHW (NPOS * HH * WW)
#define VROW 12            // window smem: cols per row (10 used)
#define VBAT 36            // window smem: floats per batch (3*12)

// Ping-pong state scratch (no device allocation allowed).
__device__ float g_state[2][BB * HH * WW];

__device__ __forceinline__ float sigmoidf(float x) {
    return __fdividef(1.0f, 1.0f + __expf(-x));
}

// 8 products for one bit-triple (va = MSB).
__device__ __forceinline__ void triple8(float va, float vb, float vc, float* P) {
    float ca = 1.0f - va, cb = 1.0f - vb, cc = 1.0f - vc;
    float t0 = cb * cc, t1 = cb * vc, t2 = vb * cc, t3 = vb * vc;
    P[0] = ca * t0; P[1] = ca * t1; P[2] = ca * t2; P[3] = ca * t3;
    P[4] = va * t0; P[5] = va * t1; P[6] = va * t2; P[7] = va * t3;
}

__global__ __launch_bounds__(THREADS, 1)
void asic_layer(const float* __restrict__ src,   // (B,H,W) previous state
                const float* __restrict__ tg,    // (NPOS,H,W) this layer's gates
                float* __restrict__ dst)         // (B,H,W)
{
    __shared__ __align__(16) float s_s[PIX * SROW];         // sigmoid(gates)
    __shared__ __align__(16) float s_v[BB * VBAT];          // state window halo

    const int tid = threadIdx.x;
    const int pixBase = blockIdx.x * PIX;
    const int hB = pixBase >> 5;         // block row
    const int w0 = pixBase & 31;         // block first col

    // ---- thread mapping: seg(16) x batch-pair(8) x pixel(8) ----
    const int seg  = tid & 15;           // A = top 4 bits of combo j
    const int bp   = (tid >> 4) & 7;     // batches bp and bp+8
    const int pixL = tid >> 7;           // 0..7
    const int pixel = pixBase + pixL;
    const int b0 = bp, b1 = bp + 8;

    // ---- issue gate LDG.128 (one combo-halfrow per thread) ----
    const int p  = tid >> 1;             // combo 0..511
    const int ih = (tid & 1) * 4;        // pixels ih..ih+3
    float4 g = *(const float4*)(tg + p * (HH * WW) + pixBase + ih);

    // ---- issue window halo LDG (480 distinct values for the whole block) ----
    // batch(16) x rows hB..hB+2 x cols w0-1..w0+8 (wrapped)
    float wv = 0.0f;
    int vIdx = 0;
    if (tid < BB * 30) {
        int b   = tid / 30;
        int rem = tid % 30;
        int r   = rem / 10;
        int c   = rem % 10;
        int row = (hB + r) & 31;
        int col = (w0 - 1 + c) & 31;
        wv = __ldg(src + b * (HH * WW) + row * WW + col);
        vIdx = b * VBAT + r * VROW + c;
    }

    // ---- sigmoid + stage gates (MUFU work overlaps the LDG latency) ----
    {
        int base = (p >> 5) * SEGROW + (p & 31);
        s_s[(ih + 0) * SROW + base] = sigmoidf(g.x);
        s_s[(ih + 1) * SROW + base] = sigmoidf(g.y);
        s_s[(ih + 2) * SROW + base] = sigmoidf(g.z);
        s_s[(ih + 3) * SROW + base] = sigmoidf(g.w);
    }
    if (tid < BB * 30) s_v[vIdx] = wv;
    __syncthreads();

    // ---- read both batches' 3x3 windows from smem (broadcast, conflict-free) ----
    float v0[9], v1[9];
#pragma unroll
    for (int i0 = 0; i0 < 3; i0++) {
#pragma unroll
        for (int i1 = 0; i1 < 3; i1++) {
            int c = i0 * VROW + pixL + i1;
            v0[i0 * 3 + i1] = s_v[b0 * VBAT + c];
            v1[i0 * 3 + i1] = s_v[b1 * VBAT + c];
        }
    }

    // ---- partial products ----
    // bit for elem m is (j >> (8-m)) & 1:
    // A = j>>5 (m0..m3, fixed = seg), B = (j>>2)&7 (m4..m6), C = j&3 (m7,m8)
    float PB0[8], PB1[8];
    triple8(v0[4], v0[5], v0[6], PB0);
    triple8(v1[4], v1[5], v1[6], PB1);

    float PC0[4], PC1[4];
    {
        float c7 = 1.0f - v0[7], c8 = 1.0f - v0[8];
        PC0[0] = c7 * c8; PC0[1] = c7 * v0[8]; PC0[2] = v0[7] * c8; PC0[3] = v0[7] * v0[8];
        float d7 = 1.0f - v1[7], d8 = 1.0f - v1[8];
        PC1[0] = d7 * d8; PC1[1] = d7 * v1[8]; PC1[2] = v1[7] * d8; PC1[3] = v1[7] * v1[8];
    }

    const float PA0 = (((seg & 8) ? v0[0] : 1.0f - v0[0]) * ((seg & 4) ? v0[1] : 1.0f - v0[1]))
                    * (((seg & 2) ? v0[2] : 1.0f - v0[2]) * ((seg & 1) ? v0[3] : 1.0f - v0[3]));
    const float PA1 = (((seg & 8) ? v1[0] : 1.0f - v1[0]) * ((seg & 4) ? v1[1] : 1.0f - v1[1]))
                    * (((seg & 2) ? v1[2] : 1.0f - v1[2]) * ((seg & 1) ? v1[3] : 1.0f - v1[3]));

    // ---- contraction: 32 combos, fma chains, each gate read feeds 2 batches ----
    const float* sp = s_s + pixL * SROW + seg * SEGROW;
    float a0e = 0.0f, a0o = 0.0f, a1e = 0.0f, a1o = 0.0f;
#pragma unroll
    for (int b = 0; b < 8; b += 2) {
        float4 r0 = *(const float4*)(sp + b * 4);
        float4 r1 = *(const float4*)(sp + b * 4 + 4);

        float i00 = PC0[0] * r0.x;
        i00 = fmaf(PC0[1], r0.y, i00);
        i00 = fmaf(PC0[2], r0.z, i00);
        i00 = fmaf(PC0[3], r0.w, i00);
        float i10 = PC1[0] * r0.x;
        i10 = fmaf(PC1[1], r0.y, i10);
        i10 = fmaf(PC1[2], r0.z, i10);
        i10 = fmaf(PC1[3], r0.w, i10);
        float i01 = PC0[0] * r1.x;
        i01 = fmaf(PC0[1], r1.y, i01);
        i01 = fmaf(PC0[2], r1.z, i01);
        i01 = fmaf(PC0[3], r1.w, i01);
        float i11 = PC1[0] * r1.x;
        i11 = fmaf(PC1[1], r1.y, i11);
        i11 = fmaf(PC1[2], r1.z, i11);
        i11 = fmaf(PC1[3], r1.w, i11);

        a0e = fmaf(PB0[b], i00, a0e);
        a1e = fmaf(PB1[b], i10, a1e);
        a0o = fmaf(PB0[b + 1], i01, a0o);
        a1o = fmaf(PB1[b + 1], i11, a1o);
    }
    float acc0 = PA0 * (a0e + a0o);
    float acc1 = PA1 * (a1e + a1o);

    // ---- reduce over the 16 A-segment lanes (seg = lane bits 0..3) ----
#pragma unroll
    for (int d = 1; d <= 8; d <<= 1) {
        acc0 += __shfl_xor_sync(0xffffffffu, acc0, d);
        acc1 += __shfl_xor_sync(0xffffffffu, acc1, d);
    }

    if (seg == 0) {
        dst[b0 * (HH * WW) + pixel] = fminf(fmaxf(acc0, 0.0f), 1.0f);
        dst[b1 * (HH * WW) + pixel] = fminf(fmaxf(acc1, 0.0f), 1.0f);
    }
}

extern "C" void kernel_launch(void* const* d_in, const int* in_sizes, int n_in,
                              void* d_out, int out_size) {
    // Identify inputs by size (x: 16384, tg: 2097152)
    const float* x  = (const float*)d_in[0];
    const float* tg = (const float*)d_in[1];
    if (n_in >= 2 && in_sizes[0] > in_sizes[1]) {
        x  = (const float*)d_in[1];
        tg = (const float*)d_in[0];
    }
    float* out = (float*)d_out;

    float* st;
    cudaGetSymbolAddress((void**)&st, g_state);
    float* s0 = st;
    float* s1 = st + BB * HH * WW;

    asic_layer<<<GRID, THREADS>>>(x,  tg + 0 * LHW, s0);
    asic_layer<<<GRID, THREADS>>>(s0, tg + 1 * LHW, s1);
    asic_layer<<<GRID, THREADS>>>(s1, tg + 2 * LHW, s0);
    asic_layer<<<GRID, THREADS>>>(s0, tg + 3 * LHW, out);
}